// round 3
// baseline (speedup 1.0000x reference)
#include <cuda_runtime.h>
#include <cuda_bf16.h>
#include <cstdint>

// Problem constants
#define BDIM   64
#define CDIM   256
#define HW     1024           // 32*32
#define KCODE  1024
#define MTILE  64             // z rows per block
#define KCHUNK 64             // codes per smem chunk
#define NCHUNK (KCODE / KCHUNK)

// smem layout (floats):
//   zt : [CDIM][MTILE]            = 16384 floats (z tile, [c][m], m contiguous)
//   et : stride-257 region, 64*257 = 16448 floats
//        - compute phase: et[k*257 + c] for k in [0,64)
//        - gather phase : et[m*257 + c] for m in [0,64)
//   red: 64 x u64 argmin keys
#define ZT_FLOATS   (CDIM * MTILE)          // 16384
#define ET_FLOATS   (64 * 257)              // 16448
#define SMEM_FLOATS (ZT_FLOATS + ET_FLOATS)
#define SMEM_BYTES  (SMEM_FLOATS * 4 + 64 * 8)

__device__ float g_esq[KCODE];

// ---------------------------------------------------------------------------
// Kernel 0: e_sq[k] = sum_c emb[k][c]^2, SEQUENTIAL fp32 mul-then-add
// (replicates XLA-CPU unfused mul + reduce). Also zero the loss slot.
// ---------------------------------------------------------------------------
__global__ void vq_esq_kernel(const float* __restrict__ emb,
                              float* __restrict__ out, int out_size, int nz) {
    int k = blockIdx.x * blockDim.x + threadIdx.x;   // grid 4 x 256
    if (k < KCODE) {
        const float* e = emb + (size_t)k * CDIM;
        float s = 0.f;
        #pragma unroll 8
        for (int c = 0; c < CDIM; ++c) {
            float v = e[c];
            s = __fadd_rn(s, __fmul_rn(v, v));       // unfused, in order
        }
        g_esq[k] = s;
    }
    if (blockIdx.x == 0 && threadIdx.x == 0 && out_size > nz)
        out[nz] = 0.0f;   // loss accumulator
}

// ---------------------------------------------------------------------------
// Main kernel: per block = 64 z rows (one b, 64 consecutive hw positions)
//   GEMM vs all 1024 codes (chunks of 64 in smem), reference-faithful
//   quantized distance, argmin (first-min tie-break), gather, loss.
// ---------------------------------------------------------------------------
__global__ __launch_bounds__(256, 1)
void vq_main_kernel(const float* __restrict__ z,
                    const float* __restrict__ emb,
                    float* __restrict__ out, int out_size, int nz) {
    extern __shared__ float smem[];
    float* zt = smem;                       // [c*64 + m]
    float* et = smem + ZT_FLOATS;           // stride-257 rows
    unsigned long long* red =
        (unsigned long long*)(smem + ZT_FLOATS + ET_FLOATS);  // [64]
    __shared__ float zsq_sm[MTILE];

    const int tid = threadIdx.x;
    const int b   = blockIdx.x >> 4;          // 16 tiles per b
    const int hw0 = (blockIdx.x & 15) * MTILE;

    // ---- load z tile: zt[c][m] = z[b][c][hw0+m], coalesced 64-float runs ----
    const float* zbase = z + (size_t)b * CDIM * HW + hw0;
    #pragma unroll 4
    for (int i = 0; i < 64; ++i) {
        int lin = i * 256 + tid;          // 16384 elems
        int c = lin >> 6;
        int m = lin & 63;
        zt[c * MTILE + m] = zbase[(size_t)c * HW + m];
    }
    __syncthreads();

    // ---- z_sq per row: SEQUENTIAL fp32, unfused mul+add (match XLA-CPU) ----
    if (tid < MTILE) {
        float s = 0.f;
        const float* zp = zt + tid;
        #pragma unroll 8
        for (int c = 0; c < CDIM; ++c) {
            float v = zp[c * MTILE];
            s = __fadd_rn(s, __fmul_rn(v, v));
        }
        zsq_sm[tid] = s;
    }
    __syncthreads();

    const int tm = tid & 15;    // row group: rows tm*4 .. tm*4+3
    const int tk = tid >> 4;    // code group: codes tk*4 .. tk*4+3 (per chunk)

    float best[4];
    int   bidx[4];
    #pragma unroll
    for (int i = 0; i < 4; ++i) { best[i] = 3.4e38f; bidx[i] = 0; }

    // per-thread z_sq copies for the 4 rows this thread owns
    float zsqr[4];
    #pragma unroll
    for (int i = 0; i < 4; ++i) zsqr[i] = zsq_sm[tm * 4 + i];

    for (int chunk = 0; chunk < NCHUNK; ++chunk) {
        // ---- load emb chunk into et[k*257 + c] (coalesced read, padded store)
        const float* ebase = emb + (size_t)chunk * KCHUNK * CDIM;
        #pragma unroll 4
        for (int i = 0; i < 64; ++i) {
            int lin = i * 256 + tid;       // 16384 elems
            int k = lin >> 8;
            int c = lin & 255;
            et[k * 257 + c] = ebase[lin];
        }
        __syncthreads();

        // ---- 4x4 register-tile dot products, ascending-c FMA chain from 0
        //      (bitwise-matches Eigen gebp sequential-K fused accumulation) ---
        float acc[4][4];
        #pragma unroll
        for (int i = 0; i < 4; ++i)
            #pragma unroll
            for (int j = 0; j < 4; ++j) acc[i][j] = 0.f;

        const float* zrow = zt + tm * 4;
        const float* e0p = et + (tk * 4 + 0) * 257;
        const float* e1p = et + (tk * 4 + 1) * 257;
        const float* e2p = et + (tk * 4 + 2) * 257;
        const float* e3p = et + (tk * 4 + 3) * 257;

        #pragma unroll 8
        for (int c = 0; c < CDIM; ++c) {
            float4 zv = *(const float4*)(zrow + c * MTILE);
            float e0 = e0p[c], e1 = e1p[c], e2 = e2p[c], e3 = e3p[c];
            acc[0][0] = __fmaf_rn(zv.x, e0, acc[0][0]);
            acc[0][1] = __fmaf_rn(zv.x, e1, acc[0][1]);
            acc[0][2] = __fmaf_rn(zv.x, e2, acc[0][2]);
            acc[0][3] = __fmaf_rn(zv.x, e3, acc[0][3]);
            acc[1][0] = __fmaf_rn(zv.y, e0, acc[1][0]);
            acc[1][1] = __fmaf_rn(zv.y, e1, acc[1][1]);
            acc[1][2] = __fmaf_rn(zv.y, e2, acc[1][2]);
            acc[1][3] = __fmaf_rn(zv.y, e3, acc[1][3]);
            acc[2][0] = __fmaf_rn(zv.z, e0, acc[2][0]);
            acc[2][1] = __fmaf_rn(zv.z, e1, acc[2][1]);
            acc[2][2] = __fmaf_rn(zv.z, e2, acc[2][2]);
            acc[2][3] = __fmaf_rn(zv.z, e3, acc[2][3]);
            acc[3][0] = __fmaf_rn(zv.w, e0, acc[3][0]);
            acc[3][1] = __fmaf_rn(zv.w, e1, acc[3][1]);
            acc[3][2] = __fmaf_rn(zv.w, e2, acc[3][2]);
            acc[3][3] = __fmaf_rn(zv.w, e3, acc[3][3]);
        }

        // ---- reference-faithful distance:
        //      d = fl( fl(z_sq + e_sq) - fl(2*e_z) ), elementwise fp32 -------
        #pragma unroll
        for (int j = 0; j < 4; ++j) {
            int kg = chunk * KCHUNK + tk * 4 + j;
            float es = g_esq[kg];
            #pragma unroll
            for (int i = 0; i < 4; ++i) {
                float u = __fadd_rn(zsqr[i], es);             // z_sq + e_sq
                float v = __fmul_rn(2.0f, acc[i][j]);          // 2*e_z (exact)
                float d = __fsub_rn(u, v);                     // final round
                if (d < best[i]) { best[i] = d; bidx[i] = kg; }  // first-min
            }
        }
        __syncthreads();   // et reads done before next chunk overwrites
    }

    // ---- cross-thread argmin reduction: ordered-uint key, idx in low bits ----
    if (tid < 64) red[tid] = 0xFFFFFFFFFFFFFFFFull;
    __syncthreads();
    #pragma unroll
    for (int i = 0; i < 4; ++i) {
        int m = tm * 4 + i;
        unsigned u = __float_as_uint(best[i]);
        u = (u & 0x80000000u) ? ~u : (u | 0x80000000u);
        unsigned long long key =
            ((unsigned long long)u << 32) | (unsigned)bidx[i];
        atomicMin(&red[m], key);
    }
    __syncthreads();

    // ---- gather stage: et[m*257 + c] = emb[idx[m]][c] (coalesced row reads) --
    for (int it = 0; it < 64; ++it) {     // one emb row per iteration
        int m = it;
        int kb = (int)(red[m] & 0xFFFFFFFFull);
        et[m * 257 + tid] = emb[(size_t)kb * CDIM + tid];
    }
    __syncthreads();

    // ---- write z_q (coalesced) + loss partial --------------------------------
    float lsum = 0.f;
    float* obase = out + (size_t)b * CDIM * HW + hw0;
    #pragma unroll 4
    for (int i = 0; i < 64; ++i) {
        int lin = i * 256 + tid;
        int c = lin >> 6;
        int m = lin & 63;
        float e = et[m * 257 + c];        // (m+c)%32 banks: conflict-free
        float zval = zt[c * MTILE + m];
        float d = e - zval;
        lsum += d * d;
        obase[(size_t)c * HW + m] = e;
    }

    // ---- block-reduce loss, atomicAdd global ---------------------------------
    __shared__ float wsum[8];
    #pragma unroll
    for (int off = 16; off > 0; off >>= 1)
        lsum += __shfl_down_sync(0xFFFFFFFFu, lsum, off);
    if ((tid & 31) == 0) wsum[tid >> 5] = lsum;
    __syncthreads();
    if (tid == 0) {
        float t = 0.f;
        #pragma unroll
        for (int w = 0; w < 8; ++w) t += wsum[w];
        if (out_size > nz) {
            // loss = (1 + BETA) * mean(diff^2), BETA = 0.25
            atomicAdd(&out[nz], t * (1.25f / 16777216.0f));
        }
    }
}

// ---------------------------------------------------------------------------
extern "C" void kernel_launch(void* const* d_in, const int* in_sizes, int n_in,
                              void* d_out, int out_size) {
    const float* z   = (const float*)d_in[0];
    const float* emb = (const float*)d_in[1];
    float* out = (float*)d_out;
    const int nz = in_sizes[0];   // 16777216 z_q elements

    // one-time opt-in to >48KB dynamic smem (runs on the correctness call,
    // before graph capture; attribute persists)
    static cudaError_t _attr = cudaFuncSetAttribute(
        vq_main_kernel, cudaFuncAttributeMaxDynamicSharedMemorySize, SMEM_BYTES);
    (void)_attr;

    vq_esq_kernel<<<4, 256>>>(emb, out, out_size, nz);
    vq_main_kernel<<<1024, 256, SMEM_BYTES>>>(z, emb, out, out_size, nz);
}

// round 4
// speedup vs baseline: 1.1663x; 1.1663x over previous
#include <cuda_runtime.h>
#include <cuda_bf16.h>
#include <cstdint>

// Problem constants
#define CDIM   256
#define HW     1024           // 32*32
#define KCODE  1024
#define MTILE  64             // z rows per block
#define KCHUNK 128            // codes per smem chunk
#define NCHUNK (KCODE / KCHUNK)
#define NTHREADS 128

// dynamic smem layout (floats):
//   zt : [CDIM][MTILE] = 16384 floats  (z tile, [c][m], m contiguous)
//   et : [KCHUNK] rows, stride 257     (compute phase; rows 0..63 reused for gather)
#define ZT_FLOATS  (CDIM * MTILE)          // 16384
#define ET_STRIDE  257
#define ET_FLOATS  (KCHUNK * ET_STRIDE)    // 32896
#define SMEM_BYTES ((ZT_FLOATS + ET_FLOATS) * 4)   // 197120 B

__device__ float g_esq[KCODE];

// ---------------------------------------------------------------------------
// packed f32x2 helpers (Blackwell FFMA2: 2x fp32 FMA per instruction,
// each lane bitwise-identical to fma.rn.f32)
// ---------------------------------------------------------------------------
__device__ __forceinline__ void ffma2(unsigned long long& acc,
                                      unsigned long long a,
                                      unsigned long long b) {
    asm("fma.rn.f32x2 %0, %1, %2, %0;" : "+l"(acc) : "l"(a), "l"(b));
}
__device__ __forceinline__ unsigned long long splat2(float e) {
    unsigned long long r;
    asm("mov.b64 %0, {%1, %1};" : "=l"(r) : "f"(e));
    return r;
}
__device__ __forceinline__ void unpack2(unsigned long long v, float& lo, float& hi) {
    asm("mov.b64 {%0, %1}, %2;" : "=f"(lo), "=f"(hi) : "l"(v));
}

// ---------------------------------------------------------------------------
// Kernel 0: e_sq[k] = sum_c emb[k][c]^2, SEQUENTIAL fp32 mul-then-add
// (replicates XLA-CPU unfused mul + reduce). Also zero the loss slot.
// ---------------------------------------------------------------------------
__global__ void vq_esq_kernel(const float* __restrict__ emb,
                              float* __restrict__ out, int out_size, int nz) {
    int k = blockIdx.x * blockDim.x + threadIdx.x;   // grid 4 x 256
    if (k < KCODE) {
        const float* e = emb + (size_t)k * CDIM;
        float s = 0.f;
        #pragma unroll 8
        for (int c = 0; c < CDIM; ++c) {
            float v = e[c];
            s = __fadd_rn(s, __fmul_rn(v, v));       // unfused, in order
        }
        g_esq[k] = s;
    }
    if (blockIdx.x == 0 && threadIdx.x == 0 && out_size > nz)
        out[nz] = 0.0f;   // loss accumulator
}

// ---------------------------------------------------------------------------
// Main kernel: 128 threads, per-thread 8 rows x 8 codes, FFMA2-packed along
// row pairs. Reference-faithful quantized distance + first-min argmin.
// ---------------------------------------------------------------------------
__global__ __launch_bounds__(NTHREADS, 1)
void vq_main_kernel(const float* __restrict__ z,
                    const float* __restrict__ emb,
                    float* __restrict__ out, int out_size, int nz) {
    extern __shared__ float smem[];
    float* zt = smem;                       // [c*64 + m]
    float* et = smem + ZT_FLOATS;           // stride-257 rows
    __shared__ float esq_sm[KCODE];
    __shared__ float zsq_sm[MTILE];
    __shared__ unsigned long long red[MTILE];
    __shared__ float wsum[4];

    const int tid = threadIdx.x;
    const int b   = blockIdx.x >> 4;          // 16 tiles per b
    const int hw0 = (blockIdx.x & 15) * MTILE;

    // ---- load z tile (vectorized): zt[c][m] = z[b][c][hw0+m] ---------------
    const float* zbase = z + (size_t)b * CDIM * HW + hw0;
    #pragma unroll
    for (int i = 0; i < 32; ++i) {
        int lin4 = i * NTHREADS + tid;        // 4096 float4
        int c  = lin4 >> 4;
        int mv = (lin4 & 15) * 4;
        float4 v = *(const float4*)(zbase + (size_t)c * HW + mv);
        *(float4*)(zt + c * MTILE + mv) = v;
    }
    // ---- preload e_sq into smem --------------------------------------------
    #pragma unroll
    for (int i = 0; i < 8; ++i)
        esq_sm[i * NTHREADS + tid] = g_esq[i * NTHREADS + tid];
    if (tid < MTILE) red[tid] = 0xFFFFFFFFFFFFFFFFull;
    __syncthreads();

    // ---- z_sq per row: SEQUENTIAL fp32, unfused mul+add (match XLA-CPU) ----
    if (tid < MTILE) {
        float s = 0.f;
        const float* zp = zt + tid;
        #pragma unroll 8
        for (int c = 0; c < CDIM; ++c) {
            float v = zp[c * MTILE];
            s = __fadd_rn(s, __fmul_rn(v, v));
        }
        zsq_sm[tid] = s;
    }
    __syncthreads();

    const int tm = tid & 7;     // row group: rows tm*8 .. tm*8+7
    const int tk = tid >> 3;    // code group: codes tk*8 .. tk*8+7 per chunk

    float best[8];
    int   bidx[8];
    #pragma unroll
    for (int i = 0; i < 8; ++i) { best[i] = 3.4e38f; bidx[i] = 0; }

    float zsqr[8];
    #pragma unroll
    for (int i = 0; i < 8; ++i) zsqr[i] = zsq_sm[tm * 8 + i];

    for (int chunk = 0; chunk < NCHUNK; ++chunk) {
        // ---- load emb chunk: gmem float4 reads, scalar stores (stride 257) -
        const float* ebase = emb + (size_t)chunk * KCHUNK * CDIM;
        #pragma unroll 8
        for (int i = 0; i < 64; ++i) {
            int lin4 = i * NTHREADS + tid;    // 8192 float4
            int k  = lin4 >> 6;
            int cv = (lin4 & 63) * 4;
            float4 v = *(const float4*)(ebase + k * CDIM + cv);
            float* d = et + k * ET_STRIDE + cv;
            d[0] = v.x; d[1] = v.y; d[2] = v.z; d[3] = v.w;
        }
        __syncthreads();

        // ---- 8x8 register tile, FFMA2-packed along row pairs ---------------
        unsigned long long acc[4][8];
        #pragma unroll
        for (int i = 0; i < 4; ++i)
            #pragma unroll
            for (int j = 0; j < 8; ++j) acc[i][j] = 0ull;

        const float* zrow = zt + tm * 8;
        const float* ecol = et + (tk * 8) * ET_STRIDE;

        #pragma unroll 4
        for (int c = 0; c < CDIM; ++c) {
            // rows tm*8..+7 packed as 4 f32x2 pairs (m contiguous in zt)
            ulonglong2 za = *(const ulonglong2*)(zrow + c * MTILE);
            ulonglong2 zb = *(const ulonglong2*)(zrow + c * MTILE + 4);
            #pragma unroll
            for (int j = 0; j < 8; ++j) {
                unsigned long long ed = splat2(ecol[j * ET_STRIDE + c]);
                ffma2(acc[0][j], za.x, ed);
                ffma2(acc[1][j], za.y, ed);
                ffma2(acc[2][j], zb.x, ed);
                ffma2(acc[3][j], zb.y, ed);
            }
        }

        // ---- reference-faithful distance:
        //      d = fl( fl(z_sq + e_sq) - fl(2*e_z) ), elementwise fp32 -------
        #pragma unroll
        for (int j = 0; j < 8; ++j) {
            int kg = chunk * KCHUNK + tk * 8 + j;
            float es = esq_sm[kg];
            #pragma unroll
            for (int i2 = 0; i2 < 4; ++i2) {
                float lo, hi;
                unpack2(acc[i2][j], lo, hi);
                int i = i2 * 2;
                float u0 = __fadd_rn(zsqr[i], es);
                float d0 = __fsub_rn(u0, __fmul_rn(2.0f, lo));
                if (d0 < best[i]) { best[i] = d0; bidx[i] = kg; }
                float u1 = __fadd_rn(zsqr[i + 1], es);
                float d1 = __fsub_rn(u1, __fmul_rn(2.0f, hi));
                if (d1 < best[i + 1]) { best[i + 1] = d1; bidx[i + 1] = kg; }
            }
        }
        __syncthreads();   // et reads done before next chunk overwrites
    }

    // ---- cross-thread argmin: ordered-uint key, idx in low bits ------------
    #pragma unroll
    for (int i = 0; i < 8; ++i) {
        int m = tm * 8 + i;
        unsigned u = __float_as_uint(best[i]);
        u = (u & 0x80000000u) ? ~u : (u | 0x80000000u);
        unsigned long long key =
            ((unsigned long long)u << 32) | (unsigned)bidx[i];
        atomicMin(&red[m], key);
    }
    __syncthreads();

    // ---- gather: et[m*257 + c] = emb[idx[m]][c] (rows 0..63 of et) ---------
    #pragma unroll 4
    for (int it = 0; it < 128; ++it) {
        int m  = it >> 1;
        int cc = (it & 1) * NTHREADS + tid;
        int kb = (int)(red[m] & 0xFFFFFFFFull);
        et[m * ET_STRIDE + cc] = emb[(size_t)kb * CDIM + cc];
    }
    __syncthreads();

    // ---- write z_q (coalesced) + loss partial ------------------------------
    float lsum = 0.f;
    float* obase = out + (size_t)b * CDIM * HW + hw0;
    #pragma unroll 4
    for (int i = 0; i < 128; ++i) {
        int lin = i * NTHREADS + tid;
        int c = lin >> 6;
        int m = lin & 63;
        float e = et[m * ET_STRIDE + c];     // (m+c)%32 banks: conflict-free
        float zval = zt[c * MTILE + m];
        float d = e - zval;
        lsum += d * d;
        obase[(size_t)c * HW + m] = e;
    }

    // ---- block-reduce loss, atomicAdd global -------------------------------
    #pragma unroll
    for (int off = 16; off > 0; off >>= 1)
        lsum += __shfl_down_sync(0xFFFFFFFFu, lsum, off);
    if ((tid & 31) == 0) wsum[tid >> 5] = lsum;
    __syncthreads();
    if (tid == 0) {
        float t = wsum[0] + wsum[1] + wsum[2] + wsum[3];
        if (out_size > nz) {
            // loss = (1 + BETA) * mean(diff^2), BETA = 0.25
            atomicAdd(&out[nz], t * (1.25f / 16777216.0f));
        }
    }
}

// ---------------------------------------------------------------------------
extern "C" void kernel_launch(void* const* d_in, const int* in_sizes, int n_in,
                              void* d_out, int out_size) {
    const float* z   = (const float*)d_in[0];
    const float* emb = (const float*)d_in[1];
    float* out = (float*)d_out;
    const int nz = in_sizes[0];   // 16777216 z_q elements

    // one-time opt-in to >48KB dynamic smem (runs on the correctness call,
    // before graph capture; attribute persists)
    static cudaError_t _attr = cudaFuncSetAttribute(
        vq_main_kernel, cudaFuncAttributeMaxDynamicSharedMemorySize, SMEM_BYTES);
    (void)_attr;

    vq_esq_kernel<<<4, 256>>>(emb, out, out_size, nz);
    vq_main_kernel<<<1024, NTHREADS, SMEM_BYTES>>>(z, emb, out, out_size, nz);
}